// round 3
// baseline (speedup 1.0000x reference)
#include <cuda_runtime.h>

#define EMB     300
#define EMB4    75          // EMB / 4
#define TASKS   12
#define WPB     8           // warps per block
#define BLK     (WPB * 32)

// Device-global scratch (no allocations allowed in kernel_launch).
__device__ int g_starts[16385 * 2];

// ---------------------------------------------------------------------------
// Fill g_starts: for sorted batch, starts[g] = lower_bound(batch, g).
// int32 vs int64 detection inlined: interpreted as int32 words, word[N-1] is
//   - int32 buffer: last (max) graph id  -> > 0
//   - int64 buffer: HIGH word of elem (N-1)/2 -> 0  (ids in [0, 2^31))
// ---------------------------------------------------------------------------
__global__ void starts_kernel(const void* __restrict__ batch, int N, int G) {
    int i = blockIdx.x * blockDim.x + threadIdx.x;
    if (i >= N) return;
    const int* b32 = (const int*)batch;
    int is64 = (b32[N - 1] == 0);

    long long cur, prev;
    if (is64) {
        const long long* b64 = (const long long*)batch;
        cur  = b64[i];
        prev = (i > 0) ? b64[i - 1] : -1;
    } else {
        cur  = b32[i];
        prev = (i > 0) ? b32[i - 1] : -1;
    }
    for (long long g = prev + 1; g <= cur; ++g) {
        if (g >= 0 && g <= (long long)G) g_starts[g] = i;
    }
    if (i == N - 1) {
        for (long long g = cur + 1; g <= (long long)G; ++g) g_starts[g] = N;
    }
}

__device__ __forceinline__ void facc(float4& a, const float4 v) {
    a.x += v.x; a.y += v.y; a.z += v.z; a.w += v.w;
}
__device__ __forceinline__ float fdot(const float4 a, const float4 v) {
    return a.x * v.x + a.y * v.y + a.z * v.z + a.w * v.w;
}

// ---------------------------------------------------------------------------
// One WARP per graph. Lane l owns float4-columns l, l+32, and l+64 (l<11).
// Streams the graph's contiguous rows (coalesced LDG.128), then computes the
// 300->12 head entirely in-warp (register dots + butterfly shfl reduction).
// No shared memory, no __syncthreads.
// ---------------------------------------------------------------------------
__global__ __launch_bounds__(BLK)
void pool_warp_kernel(const float* __restrict__ x,
                      const float* __restrict__ W,
                      const float* __restrict__ b,
                      float* __restrict__ out, int G) {
    int wg   = (blockIdx.x * BLK + threadIdx.x) >> 5;   // global warp id = graph
    int lane = threadIdx.x & 31;
    if (wg >= G) return;

    int lo = g_starts[wg];
    int hi = g_starts[wg + 1];

    const float4* __restrict__ xb = (const float4*)x;   // row r, col c: xb[r*75+c]
    const bool has2 = (lane < EMB4 - 64);               // lane < 11

    float4 a0 = make_float4(0.f,0.f,0.f,0.f), a1 = a0, a2 = a0;
    float4 c0 = a0, c1 = a0, c2 = a0;

    int r = lo;
    for (; r + 2 <= hi; r += 2) {
        const float4* row0 = xb + (size_t)r * EMB4;
        const float4* row1 = row0 + EMB4;
        float4 v0 = row0[lane];
        float4 v1 = row0[lane + 32];
        float4 u0 = row1[lane];
        float4 u1 = row1[lane + 32];
        facc(a0, v0); facc(a1, v1);
        facc(c0, u0); facc(c1, u1);
        if (has2) {
            float4 v2 = row0[lane + 64];
            float4 u2 = row1[lane + 64];
            facc(a2, v2); facc(c2, u2);
        }
    }
    if (r < hi) {
        const float4* row0 = xb + (size_t)r * EMB4;
        facc(a0, row0[lane]);
        facc(a1, row0[lane + 32]);
        if (has2) facc(a2, row0[lane + 64]);
    }
    facc(a0, c0); facc(a1, c1); facc(a2, c2);

    float inv = 1.0f / fmaxf((float)(hi - lo), 1.0f);

    // Head: 12 dot products against W rows (L1-resident), butterfly reduce.
    float res[TASKS];
    #pragma unroll
    for (int t = 0; t < TASKS; ++t) {
        const float4* wr = (const float4*)(W + t * EMB);
        float p = fdot(a0, __ldg(&wr[lane])) + fdot(a1, __ldg(&wr[lane + 32]));
        if (has2) p += fdot(a2, __ldg(&wr[lane + 64]));
        #pragma unroll
        for (int o = 16; o; o >>= 1) p += __shfl_xor_sync(0xffffffffu, p, o);
        res[t] = p * inv + b[t];
    }

    if (lane == 0) {
        float4* o4 = (float4*)(out + (size_t)wg * TASKS);   // 48B, 16B-aligned
        o4[0] = make_float4(res[0], res[1], res[2],  res[3]);
        o4[1] = make_float4(res[4], res[5], res[6],  res[7]);
        o4[2] = make_float4(res[8], res[9], res[10], res[11]);
    }
}

// ---------------------------------------------------------------------------
// kernel_launch — inputs: x [N,300] f32, batch [N] int32/int64 (sorted),
// W [12,300] f32, b [12] f32, (num_graphs scalar, unused). out: [G,12] f32.
// ---------------------------------------------------------------------------
extern "C" void kernel_launch(void* const* d_in, const int* in_sizes, int n_in,
                              void* d_out, int out_size) {
    const float* x     = (const float*)d_in[0];
    const void*  batch = d_in[1];
    const float* W     = (const float*)d_in[2];
    const float* b     = (const float*)d_in[3];
    float*       out   = (float*)d_out;

    int N = in_sizes[1];        // node count
    int G = out_size / TASKS;   // 16384

    starts_kernel<<<(N + 255) / 256, 256>>>(batch, N, G);
    pool_warp_kernel<<<(G + WPB - 1) / WPB, BLK>>>(x, W, b, out, G);
}

// round 4
// speedup vs baseline: 1.1243x; 1.1243x over previous
#include <cuda_runtime.h>
#include <cstdint>

#define EMB     300
#define EMB4    75
#define TASKS   12
#define ROWB    8                       // rows per pipeline chunk
#define CHUNKB  (ROWB * EMB * 4)        // 9600 bytes
#define NBUF    4
#define THREADS 160                     // 5 warps; 150 loader lanes

__device__ int g_starts[16385 * 2];

// ---------------------------------------------------------------------------
// starts[g] = lower_bound(sorted batch, g). int32/int64 detected via word[N-1]
// (int64 high word of last element is 0; int32 last element is max id > 0).
// ---------------------------------------------------------------------------
__global__ void starts_kernel(const void* __restrict__ batch, int N, int G) {
    int i = blockIdx.x * blockDim.x + threadIdx.x;
    if (i >= N) return;
    const int* b32 = (const int*)batch;
    int is64 = (b32[N - 1] == 0);

    long long cur, prev;
    if (is64) {
        const long long* b64 = (const long long*)batch;
        cur  = b64[i];
        prev = (i > 0) ? b64[i - 1] : -1;
    } else {
        cur  = b32[i];
        prev = (i > 0) ? b32[i - 1] : -1;
    }
    for (long long g = prev + 1; g <= cur; ++g) {
        if (g >= 0 && g <= (long long)G) g_starts[g] = i;
    }
    if (i == N - 1) {
        for (long long g = cur + 1; g <= (long long)G; ++g) g_starts[g] = N;
    }
}

// ---------------------------------------------------------------------------
// CTA per graph: cp.async.bulk 4-stage SMEM pipeline for the x stream,
// register accumulation, fused 300->12 head.
// ---------------------------------------------------------------------------
__global__ __launch_bounds__(THREADS)
void pool_pipe_kernel(const float* __restrict__ x,
                      const float* __restrict__ W,
                      const float* __restrict__ b,
                      float* __restrict__ out) {
    __shared__ alignas(16) float4 buf[NBUF][ROWB * EMB4];
    __shared__ alignas(8)  unsigned long long mbar[NBUF];
    __shared__ alignas(16) float4 sums4[150];
    __shared__ alignas(16) float  fin[EMB];

    int g = blockIdx.x;
    int t = threadIdx.x;
    int lo = g_starts[g], hi = g_starts[g + 1];
    int rows = hi - lo;
    int nchunks = (rows + ROWB - 1) / ROWB;

    uint32_t mb0 = (uint32_t)__cvta_generic_to_shared(&mbar[0]);

    if (t == 0) {
        #pragma unroll
        for (int s = 0; s < NBUF; ++s) {
            asm volatile("mbarrier.init.shared::cta.b64 [%0], 1;"
                         :: "r"(mb0 + 8u * s) : "memory");
        }
    }
    __syncthreads();

    const char* src_base = (const char*)(x + (size_t)lo * EMB);

    // producer prologue: fire up to NBUF-1 chunks ahead
    if (t == 0) {
        int pre = nchunks < (NBUF - 1) ? nchunks : (NBUF - 1);
        for (int k = 0; k < pre; ++k) {
            int r0 = k * ROWB;
            int rc = rows - r0; if (rc > ROWB) rc = ROWB;
            uint32_t bytes = (uint32_t)rc * (EMB * 4);
            uint32_t mb    = mb0 + 8u * (k & (NBUF - 1));
            uint32_t dst   = (uint32_t)__cvta_generic_to_shared(&buf[k & (NBUF - 1)][0]);
            const char* sp = src_base + (size_t)r0 * (EMB * 4);
            asm volatile("mbarrier.arrive.expect_tx.shared::cta.b64 _, [%0], %1;"
                         :: "r"(mb), "r"(bytes) : "memory");
            asm volatile("cp.async.bulk.shared::cta.global.mbarrier::complete_tx::bytes [%0], [%1], %2, [%3];"
                         :: "r"(dst), "l"(sp), "r"(bytes), "r"(mb) : "memory");
        }
    }

    int c  = t % EMB4;   // float4 column (t<150)
    int ro = t / EMB4;   // row parity 0/1
    float4 acc = make_float4(0.f, 0.f, 0.f, 0.f);

    for (int k = 0; k < nchunks; ++k) {
        int s = k & (NBUF - 1);
        uint32_t mb = mb0 + 8u * s;
        uint32_t ph = (uint32_t)((k >> 2) & 1);

        uint32_t done;
        asm volatile("{\n\t.reg .pred p;\n\t"
                     "mbarrier.try_wait.parity.acquire.cta.shared::cta.b64 p, [%1], %2;\n\t"
                     "selp.b32 %0, 1, 0, p;\n\t}"
                     : "=r"(done) : "r"(mb), "r"(ph) : "memory");
        while (!done) {
            asm volatile("{\n\t.reg .pred p;\n\t"
                         "mbarrier.try_wait.parity.acquire.cta.shared::cta.b64 p, [%1], %2, 0x989680;\n\t"
                         "selp.b32 %0, 1, 0, p;\n\t}"
                         : "=r"(done) : "r"(mb), "r"(ph) : "memory");
        }

        if (t < 150) {
            int rc = rows - k * ROWB; if (rc > ROWB) rc = ROWB;
            const float4* bp = &buf[s][0];
            #pragma unroll
            for (int r = ro; r < ROWB; r += 2) {
                if (r < rc) {
                    float4 v = bp[r * EMB4 + c];
                    acc.x += v.x; acc.y += v.y; acc.z += v.z; acc.w += v.w;
                }
            }
        }
        __syncthreads();   // all consumed buffer s; safe to refill

        if (t == 0 && k + (NBUF - 1) < nchunks) {
            asm volatile("fence.proxy.async.shared::cta;" ::: "memory");
            int kk = k + (NBUF - 1);
            int r0 = kk * ROWB;
            int rc = rows - r0; if (rc > ROWB) rc = ROWB;
            uint32_t bytes = (uint32_t)rc * (EMB * 4);
            uint32_t mbn   = mb0 + 8u * (kk & (NBUF - 1));
            uint32_t dst   = (uint32_t)__cvta_generic_to_shared(&buf[kk & (NBUF - 1)][0]);
            const char* sp = src_base + (size_t)r0 * (EMB * 4);
            asm volatile("mbarrier.arrive.expect_tx.shared::cta.b64 _, [%0], %1;"
                         :: "r"(mbn), "r"(bytes) : "memory");
            asm volatile("cp.async.bulk.shared::cta.global.mbarrier::complete_tx::bytes [%0], [%1], %2, [%3];"
                         :: "r"(dst), "l"(sp), "r"(bytes), "r"(mbn) : "memory");
        }
    }

    // reduce row-parity partials -> final column sums
    if (t < 150) sums4[t] = acc;
    __syncthreads();
    if (t < EMB4) {
        float4 a0 = sums4[t], a1 = sums4[t + EMB4];
        ((float4*)fin)[t] = make_float4(a0.x + a1.x, a0.y + a1.y,
                                        a0.z + a1.z, a0.w + a1.w);
    }
    __syncthreads();

    // fused 300->12 head: 5 warps cover 12 tasks
    int wid = t >> 5, lane = t & 31;
    float inv = 1.0f / fmaxf((float)rows, 1.0f);
    for (int task = wid; task < TASKS; task += 5) {
        const float* wr = W + task * EMB;
        float a = 0.f;
        #pragma unroll
        for (int d = lane; d < EMB; d += 32) a += fin[d] * __ldg(&wr[d]);
        #pragma unroll
        for (int o = 16; o; o >>= 1) a += __shfl_xor_sync(0xffffffffu, a, o);
        if (lane == 0) out[(size_t)g * TASKS + task] = a * inv + b[task];
    }
}

// ---------------------------------------------------------------------------
extern "C" void kernel_launch(void* const* d_in, const int* in_sizes, int n_in,
                              void* d_out, int out_size) {
    const float* x     = (const float*)d_in[0];
    const void*  batch = d_in[1];
    const float* W     = (const float*)d_in[2];
    const float* b     = (const float*)d_in[3];
    float*       out   = (float*)d_out;

    int N = in_sizes[1];
    int G = out_size / TASKS;

    starts_kernel<<<(N + 255) / 256, 256>>>(batch, N, G);
    pool_pipe_kernel<<<G, THREADS>>>(x, W, b, out);
}